// round 1
// baseline (speedup 1.0000x reference)
#include <cuda_runtime.h>
#include <cstdint>

// Problem constants (fixed by the dataset)
#define N_NODES 100000
#define N_EDGES 600000
#define IN_C  128
#define HID_C 128
#define OUT_C 64

// ---------------- scratch (static device globals; no allocation allowed) ----
__device__ float g_deg [N_NODES];
__device__ float g_dinv[N_NODES];
__device__ float g_h1s [(size_t)N_NODES * HID_C];  // (x@W1) * dinv[row]
__device__ float g_t1  [(size_t)N_NODES * HID_C];  // edge-accumulated sum, layer 1
__device__ float g_h2s [(size_t)N_NODES * OUT_C];  // (a1@W2) * dinv[row]
__device__ float g_t2  [(size_t)N_NODES * OUT_C];  // edge-accumulated sum, layer 2

// ---------------- degree / dinv --------------------------------------------
__global__ void deg_init_kernel(int n) {
    int i = blockIdx.x * blockDim.x + threadIdx.x;
    if (i < n) g_deg[i] = 1.0f;  // self loop
}

__global__ void deg_count_kernel(const int* __restrict__ dst, int E) {
    int e = blockIdx.x * blockDim.x + threadIdx.x;
    if (e < E) atomicAdd(&g_deg[dst[e]], 1.0f);
}

__global__ void dinv_kernel(int n) {
    int i = blockIdx.x * blockDim.x + threadIdx.x;
    if (i < n) g_dinv[i] = rsqrtf(g_deg[i]);
}

// ---------------- GEMM1: h1s = (x @ W1) * dinv[row]; t1 = 0 ----------------
// Block tile: M=64, N=128 (full), K chunked by 32. 256 threads, 8x4 microtile.
__global__ __launch_bounds__(256) void gemm1_kernel(const float* __restrict__ x,
                                                    const float* __restrict__ W1,
                                                    int n_nodes) {
    __shared__ float As[32][65];    // [k][r], pad 65 -> conflict-free transpose store
    __shared__ float Bs[32][128];   // [k][n]

    const int block_row = blockIdx.x * 64;
    const int tx = threadIdx.x & 31;   // col group: cols tx*4 .. tx*4+3
    const int ty = threadIdx.x >> 5;   // row group: rows ty*8 .. ty*8+7

    float acc[8][4];
#pragma unroll
    for (int i = 0; i < 8; i++)
#pragma unroll
        for (int j = 0; j < 4; j++) acc[i][j] = 0.0f;

    for (int kc = 0; kc < IN_C; kc += 32) {
        // Load A tile (64 rows x 32 k), transposed into As[k][r]
        {
            const int k  = threadIdx.x & 31;
            const int r0 = threadIdx.x >> 5;   // 0..7
#pragma unroll
            for (int rr = 0; rr < 64; rr += 8) {
                const int r = r0 + rr;
                const int grow = block_row + r;
                float v = 0.0f;
                if (grow < n_nodes) v = x[(size_t)grow * IN_C + kc + k];
                As[k][r] = v;
            }
        }
        // Load B tile (32 k x 128 n) as float4
        {
            const int n4 = (threadIdx.x & 31) * 4;
            const int k0 = threadIdx.x >> 5;   // 0..7
#pragma unroll
            for (int kk = 0; kk < 32; kk += 8) {
                const int k = k0 + kk;
                float4 v = *(const float4*)&W1[(size_t)(kc + k) * HID_C + n4];
                *(float4*)&Bs[k][n4] = v;
            }
        }
        __syncthreads();

#pragma unroll
        for (int k = 0; k < 32; k++) {
            const float4 bv = *(const float4*)&Bs[k][tx * 4];
            float a[8];
#pragma unroll
            for (int i = 0; i < 8; i++) a[i] = As[k][ty * 8 + i];
#pragma unroll
            for (int i = 0; i < 8; i++) {
                acc[i][0] += a[i] * bv.x;
                acc[i][1] += a[i] * bv.y;
                acc[i][2] += a[i] * bv.z;
                acc[i][3] += a[i] * bv.w;
            }
        }
        __syncthreads();
    }

    // Epilogue: scale by dinv[row], store h1s, zero t1
    const int c = tx * 4;
#pragma unroll
    for (int i = 0; i < 8; i++) {
        const int r = block_row + ty * 8 + i;
        if (r < n_nodes) {
            const float di = g_dinv[r];
            float4 o;
            o.x = acc[i][0] * di; o.y = acc[i][1] * di;
            o.z = acc[i][2] * di; o.w = acc[i][3] * di;
            *(float4*)&g_h1s[(size_t)r * HID_C + c] = o;
            *(float4*)&g_t1 [(size_t)r * HID_C + c] = make_float4(0.f, 0.f, 0.f, 0.f);
        }
    }
}

// ---------------- Edge scatter layer 1: t1[d] += h1s[s] (warp per edge) ----
__global__ __launch_bounds__(256) void edge1_kernel(const int* __restrict__ src,
                                                    const int* __restrict__ dst,
                                                    int E) {
    const int idx  = blockIdx.x * blockDim.x + threadIdx.x;
    const int e    = idx >> 5;
    if (e >= E) return;
    const int lane = idx & 31;
    const int s = __ldg(&src[e]);
    const int d = __ldg(&dst[e]);
    const float4 v = *(const float4*)&g_h1s[(size_t)s * HID_C + lane * 4];
    float4* p = (float4*)&g_t1[(size_t)d * HID_C + lane * 4];
    asm volatile("red.global.add.v4.f32 [%0], {%1, %2, %3, %4};"
                 :: "l"(p), "f"(v.x), "f"(v.y), "f"(v.z), "f"(v.w)
                 : "memory");
}

// ---------------- GEMM2: a1 = relu(dinv*(t1+h1s)+b1); h2s = (a1@W2)*dinv ---
// Block tile: M=128, N=64 (full), K chunked by 32. 256 threads, 8x4 microtile.
__global__ __launch_bounds__(256) void gemm2_kernel(const float* __restrict__ W2,
                                                    const float* __restrict__ b1,
                                                    int n_nodes) {
    __shared__ float As[32][129];   // [k][r], pad -> conflict-free transpose store
    __shared__ float Bs[32][64];    // [k][n]

    const int block_row = blockIdx.x * 128;
    const int tx = threadIdx.x & 15;   // col group: cols tx*4 .. tx*4+3
    const int ty = threadIdx.x >> 4;   // row group: rows ty*8 .. ty*8+7 (0..15)

    float acc[8][4];
#pragma unroll
    for (int i = 0; i < 8; i++)
#pragma unroll
        for (int j = 0; j < 4; j++) acc[i][j] = 0.0f;

    for (int kc = 0; kc < HID_C; kc += 32) {
        // Build A tile on the fly: a1[r][k] = relu(dinv[r]*(t1+h1s) + b1[k])
        {
            const int k  = threadIdx.x & 31;
            const int r0 = threadIdx.x >> 5;    // 0..7
            const float bk = b1[kc + k];
#pragma unroll
            for (int rr = 0; rr < 128; rr += 8) {
                const int r = r0 + rr;
                const int grow = block_row + r;
                float v = 0.0f;
                if (grow < n_nodes) {
                    const size_t ix = (size_t)grow * HID_C + kc + k;
                    const float pre = g_dinv[grow] * (g_t1[ix] + g_h1s[ix]) + bk;
                    v = fmaxf(pre, 0.0f);
                }
                As[k][r] = v;
            }
        }
        // Load B tile (32 k x 64 n)
        {
            const int n4 = (threadIdx.x & 15) * 4;
            const int k0 = threadIdx.x >> 4;    // 0..15
#pragma unroll
            for (int kk = 0; kk < 32; kk += 16) {
                const int k = k0 + kk;
                float4 v = *(const float4*)&W2[(size_t)(kc + k) * OUT_C + n4];
                *(float4*)&Bs[k][n4] = v;
            }
        }
        __syncthreads();

#pragma unroll
        for (int k = 0; k < 32; k++) {
            const float4 bv = *(const float4*)&Bs[k][tx * 4];
            float a[8];
#pragma unroll
            for (int i = 0; i < 8; i++) a[i] = As[k][ty * 8 + i];
#pragma unroll
            for (int i = 0; i < 8; i++) {
                acc[i][0] += a[i] * bv.x;
                acc[i][1] += a[i] * bv.y;
                acc[i][2] += a[i] * bv.z;
                acc[i][3] += a[i] * bv.w;
            }
        }
        __syncthreads();
    }

    const int c = tx * 4;
#pragma unroll
    for (int i = 0; i < 8; i++) {
        const int r = block_row + ty * 8 + i;
        if (r < n_nodes) {
            const float di = g_dinv[r];
            float4 o;
            o.x = acc[i][0] * di; o.y = acc[i][1] * di;
            o.z = acc[i][2] * di; o.w = acc[i][3] * di;
            *(float4*)&g_h2s[(size_t)r * OUT_C + c] = o;
            *(float4*)&g_t2 [(size_t)r * OUT_C + c] = make_float4(0.f, 0.f, 0.f, 0.f);
        }
    }
}

// ---------------- Edge scatter layer 2: t2[d] += h2s[s] (16 lanes/edge) ----
__global__ __launch_bounds__(256) void edge2_kernel(const int* __restrict__ src,
                                                    const int* __restrict__ dst,
                                                    int E) {
    const int idx  = blockIdx.x * blockDim.x + threadIdx.x;
    const int e    = idx >> 4;
    if (e >= E) return;
    const int lane = idx & 15;
    const int s = __ldg(&src[e]);
    const int d = __ldg(&dst[e]);
    const float4 v = *(const float4*)&g_h2s[(size_t)s * OUT_C + lane * 4];
    float4* p = (float4*)&g_t2[(size_t)d * OUT_C + lane * 4];
    asm volatile("red.global.add.v4.f32 [%0], {%1, %2, %3, %4};"
                 :: "l"(p), "f"(v.x), "f"(v.y), "f"(v.z), "f"(v.w)
                 : "memory");
}

// ---------------- Final: out = dinv*(t2+h2s) + b2 ---------------------------
__global__ __launch_bounds__(256) void final_kernel(const float* __restrict__ b2,
                                                    float* __restrict__ out,
                                                    int n_nodes) {
    const int i = blockIdx.x * blockDim.x + threadIdx.x;  // one float4 per thread
    const int total = n_nodes * (OUT_C / 4);
    if (i >= total) return;
    const int r  = i / (OUT_C / 4);
    const int c4 = (i % (OUT_C / 4)) * 4;
    const float di = g_dinv[r];
    const float4 t = *(const float4*)&g_t2 [(size_t)r * OUT_C + c4];
    const float4 h = *(const float4*)&g_h2s[(size_t)r * OUT_C + c4];
    const float4 bb = *(const float4*)&b2[c4];
    float4 o;
    o.x = di * (t.x + h.x) + bb.x;
    o.y = di * (t.y + h.y) + bb.y;
    o.z = di * (t.z + h.z) + bb.z;
    o.w = di * (t.w + h.w) + bb.w;
    *(float4*)&out[(size_t)r * OUT_C + c4] = o;
}

// ---------------- launch ----------------------------------------------------
extern "C" void kernel_launch(void* const* d_in, const int* in_sizes, int n_in,
                              void* d_out, int out_size) {
    const float* x   = (const float*)d_in[0];
    const float* W1  = (const float*)d_in[1];
    const float* b1  = (const float*)d_in[2];
    const float* W2  = (const float*)d_in[3];
    const float* b2  = (const float*)d_in[4];
    const int*   src = (const int*)  d_in[5];
    const int*   dst = (const int*)  d_in[6];
    float*       out = (float*)d_out;

    const int n = in_sizes[0] / IN_C;   // 100000
    const int E = in_sizes[5];          // 600000

    // degree + dinv
    deg_init_kernel<<<(n + 255) / 256, 256>>>(n);
    deg_count_kernel<<<(E + 255) / 256, 256>>>(dst, E);
    dinv_kernel<<<(n + 255) / 256, 256>>>(n);

    // layer 1
    gemm1_kernel<<<(n + 63) / 64, 256>>>(x, W1, n);
    {
        long long threads = (long long)E * 32;
        edge1_kernel<<<(int)((threads + 255) / 256), 256>>>(src, dst, E);
    }

    // layer 2
    gemm2_kernel<<<(n + 127) / 128, 256>>>(W2, b1, n);
    {
        long long threads = (long long)E * 16;
        edge2_kernel<<<(int)((threads + 255) / 256), 256>>>(src, dst, E);
    }

    // final combine
    {
        int total = n * (OUT_C / 4);
        final_kernel<<<(total + 255) / 256, 256>>>(b2, out, n);
    }
}

// round 4
// speedup vs baseline: 1.3084x; 1.3084x over previous
#include <cuda_runtime.h>
#include <cuda_bf16.h>
#include <cstdint>

// Problem constants (fixed by the dataset)
#define N_NODES 100000
#define N_EDGES 600000
#define IN_C  128
#define HID_C 128
#define OUT_C 64

// ===================== scratch (static device globals) ======================
__device__ float g_deg [N_NODES];
__device__ float g_dinv[N_NODES];
__device__ float g_h1s [(size_t)N_NODES * HID_C];  // (x@W1) * dinv[row]
__device__ float g_t1  [(size_t)N_NODES * HID_C];  // edge sums, layer 1
__device__ float g_h2s [(size_t)N_NODES * OUT_C];  // (a1@W2) * dinv[row]
__device__ float g_t2  [(size_t)N_NODES * OUT_C];  // edge sums, layer 2

// Pre-swizzled transposed split weights: row n (output ch), 128 bf16 k's,
// 256 B/row, 16B-block XOR swizzle: blk' = blk ^ (n & 7).
__device__ __align__(128) unsigned char g_B1hi[HID_C * 256];   // 32768 B
__device__ __align__(128) unsigned char g_B1lo[HID_C * 256];
__device__ __align__(128) unsigned char g_B2hi[OUT_C * 256];   // 16384 B
__device__ __align__(128) unsigned char g_B2lo[OUT_C * 256];

__device__ __forceinline__ uint32_t sw_off(int row, int k) {
    // byte offset of element k (bf16) in swizzled 256B row
    return (uint32_t)row * 256u + ((((uint32_t)k >> 3) ^ ((uint32_t)row & 7u)) << 4)
         + ((uint32_t)k & 7u) * 2u;
}

__device__ __forceinline__ uint32_t smem_u32(const void* p) {
    uint32_t a;
    asm("{ .reg .u64 t; cvta.to.shared.u64 t, %1; cvt.u32.u64 %0, t; }" : "=r"(a) : "l"(p));
    return a;
}

__device__ __forceinline__ void ldsm_x4(uint32_t& r0, uint32_t& r1,
                                        uint32_t& r2, uint32_t& r3, uint32_t addr) {
    asm volatile("ldmatrix.sync.aligned.m8n8.x4.shared.b16 {%0,%1,%2,%3}, [%4];"
                 : "=r"(r0), "=r"(r1), "=r"(r2), "=r"(r3) : "r"(addr));
}

__device__ __forceinline__ void mma_bf16(float& c0, float& c1, float& c2, float& c3,
                                         uint32_t a0, uint32_t a1, uint32_t a2, uint32_t a3,
                                         uint32_t b0, uint32_t b1) {
    asm volatile("mma.sync.aligned.m16n8k16.row.col.f32.bf16.bf16.f32 "
                 "{%0,%1,%2,%3}, {%4,%5,%6,%7}, {%8,%9}, {%0,%1,%2,%3};"
                 : "+f"(c0), "+f"(c1), "+f"(c2), "+f"(c3)
                 : "r"(a0), "r"(a1), "r"(a2), "r"(a3), "r"(b0), "r"(b1));
}

__device__ __forceinline__ uint32_t pack_bf2(float a, float b) {
    __nv_bfloat162 p = __halves2bfloat162(__float2bfloat16(a), __float2bfloat16(b));
    return *(uint32_t*)&p;
}
__device__ __forceinline__ void split2(float a, float b, uint32_t& hi, uint32_t& lo) {
    __nv_bfloat16 ha = __float2bfloat16(a);
    __nv_bfloat16 hb = __float2bfloat16(b);
    __nv_bfloat162 h = __halves2bfloat162(ha, hb);
    __nv_bfloat162 l = __halves2bfloat162(__float2bfloat16(a - __bfloat162float(ha)),
                                          __float2bfloat16(b - __bfloat162float(hb)));
    hi = *(uint32_t*)&h;
    lo = *(uint32_t*)&l;
}

// ===================== weight prep: transpose + bf16 split + swizzle ========
__global__ void prep_kernel(const float* __restrict__ W1,
                            const float* __restrict__ W2) {
    const int i = blockIdx.x * blockDim.x + threadIdx.x;
    if (i < IN_C * HID_C) {
        const int k = i >> 7;        // input channel
        const int n = i & 127;       // output channel
        const float v = W1[k * HID_C + n];
        const __nv_bfloat16 h = __float2bfloat16(v);
        const __nv_bfloat16 l = __float2bfloat16(v - __bfloat162float(h));
        const uint32_t off = sw_off(n, k);
        *(__nv_bfloat16*)(g_B1hi + off) = h;
        *(__nv_bfloat16*)(g_B1lo + off) = l;
    } else if (i < IN_C * HID_C + HID_C * OUT_C) {
        const int j = i - IN_C * HID_C;
        const int k = j >> 6;
        const int n = j & 63;
        const float v = W2[k * OUT_C + n];
        const __nv_bfloat16 h = __float2bfloat16(v);
        const __nv_bfloat16 l = __float2bfloat16(v - __bfloat162float(h));
        const uint32_t off = sw_off(n, k);
        *(__nv_bfloat16*)(g_B2hi + off) = h;
        *(__nv_bfloat16*)(g_B2lo + off) = l;
    }
}

// ===================== degree / dinv ========================================
__global__ void deg_init_kernel(int n) {
    int i = blockIdx.x * blockDim.x + threadIdx.x;
    if (i < n) g_deg[i] = 1.0f;  // self loop
}
__global__ void deg_count_kernel(const int* __restrict__ dst, int E) {
    int e = blockIdx.x * blockDim.x + threadIdx.x;
    if (e < E) atomicAdd(&g_deg[dst[e]], 1.0f);
}
__global__ void dinv_kernel(int n) {
    int i = blockIdx.x * blockDim.x + threadIdx.x;
    if (i < n) g_dinv[i] = rsqrtf(g_deg[i]);
}

// ===================== GEMM core (warp mma, bf16 split, 3 terms) ============
// 256 threads = 8 warps, warp grid 4(M) x 2(N). M_TILE = 128 rows.
// NT = number of n8 tiles per warp (8 for N=128, 4 for N=64).
template <int NC, int NT>
__device__ __forceinline__ void gemm_compute_epilogue(
    uint32_t sA_hi, uint32_t sA_lo, uint32_t sB_hi, uint32_t sB_lo,
    int block_row, int n_nodes,
    float* __restrict__ gh, float* __restrict__ gt)
{
    const int tid = threadIdx.x;
    const int wid = tid >> 5;
    const int l   = tid & 31;
    const int mw  = wid >> 1;          // 0..3
    const int nw  = wid & 1;           // 0..1
    const int mbase = mw * 32;
    const int nbase = nw * (NT * 8);
    const int tg = l >> 2;             // 0..7
    const int tp = l & 3;              // 0..3

    float acc[2][NT][4];
#pragma unroll
    for (int mt = 0; mt < 2; mt++)
#pragma unroll
        for (int nt = 0; nt < NT; nt++)
#pragma unroll
            for (int c = 0; c < 4; c++) acc[mt][nt][c] = 0.0f;

    // Per-lane address components
    const int a_row_in = l & 15;          // row within m16 tile
    const int a_kb_add = l >> 4;          // +0/+1 16B block
    const int b_nrow   = l & 7;           // row within n8 tile
    const int b_nt_add = l >> 4;          // tile select within x4 pair
    const int b_kb_add = (l >> 3) & 1;

#pragma unroll
    for (int ks = 0; ks < 8; ks++) {
        const int kb0 = ks * 2;
        uint32_t ah[2][4], al[2][4];
#pragma unroll
        for (int mt = 0; mt < 2; mt++) {
            const int row = mbase + mt * 16 + a_row_in;
            const uint32_t off = (uint32_t)row * 256u
                + ((uint32_t)((kb0 + a_kb_add) ^ (row & 7)) << 4);
            ldsm_x4(ah[mt][0], ah[mt][1], ah[mt][2], ah[mt][3], sA_hi + off);
            ldsm_x4(al[mt][0], al[mt][1], al[mt][2], al[mt][3], sA_lo + off);
        }
        uint32_t bh[NT][2], bl[NT][2];
#pragma unroll
        for (int j = 0; j < NT / 2; j++) {
            const int n = nbase + (2 * j + b_nt_add) * 8 + b_nrow;
            const uint32_t off = (uint32_t)n * 256u
                + ((uint32_t)((kb0 + b_kb_add) ^ (n & 7)) << 4);
            ldsm_x4(bh[2*j][0], bh[2*j][1], bh[2*j+1][0], bh[2*j+1][1], sB_hi + off);
            ldsm_x4(bl[2*j][0], bl[2*j][1], bl[2*j+1][0], bl[2*j+1][1], sB_lo + off);
        }
#pragma unroll
        for (int mt = 0; mt < 2; mt++)
#pragma unroll
            for (int nt = 0; nt < NT; nt++) {
                mma_bf16(acc[mt][nt][0], acc[mt][nt][1], acc[mt][nt][2], acc[mt][nt][3],
                         ah[mt][0], ah[mt][1], ah[mt][2], ah[mt][3], bh[nt][0], bh[nt][1]);
                mma_bf16(acc[mt][nt][0], acc[mt][nt][1], acc[mt][nt][2], acc[mt][nt][3],
                         al[mt][0], al[mt][1], al[mt][2], al[mt][3], bh[nt][0], bh[nt][1]);
                mma_bf16(acc[mt][nt][0], acc[mt][nt][1], acc[mt][nt][2], acc[mt][nt][3],
                         ah[mt][0], ah[mt][1], ah[mt][2], ah[mt][3], bl[nt][0], bl[nt][1]);
            }
    }

    // Epilogue: out = acc * dinv[row]; gt = 0
#pragma unroll
    for (int mt = 0; mt < 2; mt++) {
        const int r0 = block_row + mbase + mt * 16 + tg;
        const int r1 = r0 + 8;
        const bool v0 = r0 < n_nodes;
        const bool v1 = r1 < n_nodes;
        const float d0 = v0 ? g_dinv[r0] : 0.0f;
        const float d1 = v1 ? g_dinv[r1] : 0.0f;
#pragma unroll
        for (int nt = 0; nt < NT; nt++) {
            const int col = nbase + nt * 8 + tp * 2;
            if (v0) {
                float2 o; o.x = acc[mt][nt][0] * d0; o.y = acc[mt][nt][1] * d0;
                *(float2*)&gh[(size_t)r0 * NC + col] = o;
                *(float2*)&gt[(size_t)r0 * NC + col] = make_float2(0.f, 0.f);
            }
            if (v1) {
                float2 o; o.x = acc[mt][nt][2] * d1; o.y = acc[mt][nt][3] * d1;
                *(float2*)&gh[(size_t)r1 * NC + col] = o;
                *(float2*)&gt[(size_t)r1 * NC + col] = make_float2(0.f, 0.f);
            }
        }
    }
}

// ===================== GEMM1: h1s = (x@W1)*dinv; t1 = 0 =====================
__global__ __launch_bounds__(256) void gemm1_kernel(const float* __restrict__ x,
                                                    int n_nodes) {
    extern __shared__ char smem[];
    const uint32_t sbase = smem_u32(smem);
    const uint32_t sA_hi = sbase;
    const uint32_t sA_lo = sbase + 32768;
    const uint32_t sB_hi = sbase + 65536;
    const uint32_t sB_lo = sbase + 98304;

    const int tid = threadIdx.x;
    const int block_row = blockIdx.x * 128;

    // Copy pre-swizzled B (32 KB x2)
    {
        const uint4* sh = (const uint4*)g_B1hi;
        const uint4* sl = (const uint4*)g_B1lo;
        uint4* dh = (uint4*)(smem + 65536);
        uint4* dl = (uint4*)(smem + 98304);
#pragma unroll
        for (int i = tid; i < 2048; i += 256) { dh[i] = sh[i]; dl[i] = sl[i]; }
    }

    // Stage A: 128 rows x 128 fp32 -> bf16 hi/lo, swizzled
    {
        const int l = tid & 31;             // float4 index within row
        const int w = tid >> 5;
        uint2* Ah = (uint2*)smem;
        uint2* Al = (uint2*)(smem + 32768);
#pragma unroll
        for (int p = 0; p < 16; p++) {
            const int r = w + 8 * p;
            const int grow = block_row + r;
            float4 v = make_float4(0.f, 0.f, 0.f, 0.f);
            if (grow < n_nodes) v = *(const float4*)&x[(size_t)grow * IN_C + 4 * l];
            uint2 h, lo;
            split2(v.x, v.y, h.x, lo.x);
            split2(v.z, v.w, h.y, lo.y);
            const uint32_t off = ((uint32_t)r * 256u
                + ((uint32_t)((l >> 1) ^ (r & 7)) << 4) + (uint32_t)(l & 1) * 8u) >> 3;
            Ah[off] = h;
            Al[off] = lo;
        }
    }
    __syncthreads();

    gemm_compute_epilogue<HID_C, 8>(sA_hi, sA_lo, sB_hi, sB_lo,
                                    block_row, n_nodes, g_h1s, g_t1);
}

// ===================== Edge scatter layer 1 (warp/edge) =====================
__global__ __launch_bounds__(256) void edge1_kernel(const int* __restrict__ src,
                                                    const int* __restrict__ dst,
                                                    int E) {
    const int idx  = blockIdx.x * blockDim.x + threadIdx.x;
    const int e    = idx >> 5;
    if (e >= E) return;
    const int lane = idx & 31;
    const int s = __ldg(&src[e]);
    const int d = __ldg(&dst[e]);
    const float4 v = *(const float4*)&g_h1s[(size_t)s * HID_C + lane * 4];
    float4* p = (float4*)&g_t1[(size_t)d * HID_C + lane * 4];
    asm volatile("red.global.add.v4.f32 [%0], {%1, %2, %3, %4};"
                 :: "l"(p), "f"(v.x), "f"(v.y), "f"(v.z), "f"(v.w)
                 : "memory");
}

// ===================== GEMM2: a1 = relu(dinv*(t1+h1s)+b1); h2s ==============
__global__ __launch_bounds__(256) void gemm2_kernel(const float* __restrict__ b1,
                                                    int n_nodes) {
    extern __shared__ char smem[];
    const uint32_t sbase = smem_u32(smem);
    const uint32_t sA_hi = sbase;
    const uint32_t sA_lo = sbase + 32768;
    const uint32_t sB_hi = sbase + 65536;
    const uint32_t sB_lo = sbase + 81920;

    const int tid = threadIdx.x;
    const int block_row = blockIdx.x * 128;

    // Copy pre-swizzled B (16 KB x2)
    {
        const uint4* sh = (const uint4*)g_B2hi;
        const uint4* sl = (const uint4*)g_B2lo;
        uint4* dh = (uint4*)(smem + 65536);
        uint4* dl = (uint4*)(smem + 81920);
#pragma unroll
        for (int i = tid; i < 1024; i += 256) { dh[i] = sh[i]; dl[i] = sl[i]; }
    }

    // Stage A: a1 = relu(dinv*(t1+h1s)+b1), split hi/lo
    {
        const int l = tid & 31;
        const int w = tid >> 5;
        uint2* Ah = (uint2*)smem;
        uint2* Al = (uint2*)(smem + 32768);
#pragma unroll
        for (int p = 0; p < 16; p++) {
            const int r = w + 8 * p;
            const int grow = block_row + r;
            float4 a = make_float4(0.f, 0.f, 0.f, 0.f);
            if (grow < n_nodes) {
                const float dg = g_dinv[grow];
                const float4 t = *(const float4*)&g_t1 [(size_t)grow * HID_C + 4 * l];
                const float4 h = *(const float4*)&g_h1s[(size_t)grow * HID_C + 4 * l];
                const float4 b = *(const float4*)&b1[4 * l];
                a.x = fmaxf(dg * (t.x + h.x) + b.x, 0.0f);
                a.y = fmaxf(dg * (t.y + h.y) + b.y, 0.0f);
                a.z = fmaxf(dg * (t.z + h.z) + b.z, 0.0f);
                a.w = fmaxf(dg * (t.w + h.w) + b.w, 0.0f);
            }
            uint2 h2, lo;
            split2(a.x, a.y, h2.x, lo.x);
            split2(a.z, a.w, h2.y, lo.y);
            const uint32_t off = ((uint32_t)r * 256u
                + ((uint32_t)((l >> 1) ^ (r & 7)) << 4) + (uint32_t)(l & 1) * 8u) >> 3;
            Ah[off] = h2;
            Al[off] = lo;
        }
    }
    __syncthreads();

    gemm_compute_epilogue<OUT_C, 4>(sA_hi, sA_lo, sB_hi, sB_lo,
                                    block_row, n_nodes, g_h2s, g_t2);
}

// ===================== Edge scatter layer 2 (16 lanes/edge) =================
__global__ __launch_bounds__(256) void edge2_kernel(const int* __restrict__ src,
                                                    const int* __restrict__ dst,
                                                    int E) {
    const int idx  = blockIdx.x * blockDim.x + threadIdx.x;
    const int e    = idx >> 4;
    if (e >= E) return;
    const int lane = idx & 15;
    const int s = __ldg(&src[e]);
    const int d = __ldg(&dst[e]);
    const float4 v = *(const float4*)&g_h2s[(size_t)s * OUT_C + lane * 4];
    float4* p = (float4*)&g_t2[(size_t)d * OUT_C + lane * 4];
    asm volatile("red.global.add.v4.f32 [%0], {%1, %2, %3, %4};"
                 :: "l"(p), "f"(v.x), "f"(v.y), "f"(v.z), "f"(v.w)
                 : "memory");
}

// ===================== Final: out = dinv*(t2+h2s) + b2 ======================
__global__ __launch_bounds__(256) void final_kernel(const float* __restrict__ b2,
                                                    float* __restrict__ out,
                                                    int n_nodes) {
    const int i = blockIdx.x * blockDim.x + threadIdx.x;
    const int total = n_nodes * (OUT_C / 4);
    if (i >= total) return;
    const int r  = i / (OUT_C / 4);
    const int c4 = (i % (OUT_C / 4)) * 4;
    const float di = g_dinv[r];
    const float4 t = *(const float4*)&g_t2 [(size_t)r * OUT_C + c4];
    const float4 h = *(const float4*)&g_h2s[(size_t)r * OUT_C + c4];
    const float4 bb = *(const float4*)&b2[c4];
    float4 o;
    o.x = di * (t.x + h.x) + bb.x;
    o.y = di * (t.y + h.y) + bb.y;
    o.z = di * (t.z + h.z) + bb.z;
    o.w = di * (t.w + h.w) + bb.w;
    *(float4*)&out[(size_t)r * OUT_C + c4] = o;
}

// ===================== launch ===============================================
extern "C" void kernel_launch(void* const* d_in, const int* in_sizes, int n_in,
                              void* d_out, int out_size) {
    const float* x   = (const float*)d_in[0];
    const float* W1  = (const float*)d_in[1];
    const float* b1  = (const float*)d_in[2];
    const float* W2  = (const float*)d_in[3];
    const float* b2  = (const float*)d_in[4];
    const int*   src = (const int*)  d_in[5];
    const int*   dst = (const int*)  d_in[6];
    float*       out = (float*)d_out;

    const int n = in_sizes[0] / IN_C;   // 100000
    const int E = in_sizes[5];          // 600000

    static bool attr_done = false;
    if (!attr_done) {
        cudaFuncSetAttribute(gemm1_kernel,
                             cudaFuncAttributeMaxDynamicSharedMemorySize, 131072);
        cudaFuncSetAttribute(gemm2_kernel,
                             cudaFuncAttributeMaxDynamicSharedMemorySize, 98304);
        attr_done = true;
    }

    // weight prep + degree + dinv
    prep_kernel<<<(IN_C * HID_C + HID_C * OUT_C + 255) / 256, 256>>>(W1, W2);
    deg_init_kernel<<<(n + 255) / 256, 256>>>(n);
    deg_count_kernel<<<(E + 255) / 256, 256>>>(dst, E);
    dinv_kernel<<<(n + 255) / 256, 256>>>(n);

    const int tiles = (n + 127) / 128;

    // layer 1
    gemm1_kernel<<<tiles, 256, 131072>>>(x, n);
    {
        long long threads = (long long)E * 32;
        edge1_kernel<<<(int)((threads + 255) / 256), 256>>>(src, dst, E);
    }

    // layer 2
    gemm2_kernel<<<tiles, 256, 98304>>>(b1, n);
    {
        long long threads = (long long)E * 16;
        edge2_kernel<<<(int)((threads + 255) / 256), 256>>>(src, dst, E);
    }

    // final combine
    {
        int total = n * (OUT_C / 4);
        final_kernel<<<(total + 255) / 256, 256>>>(b2, out, n);
    }
}

// round 5
// speedup vs baseline: 1.9151x; 1.4637x over previous
#include <cuda_runtime.h>
#include <cuda_bf16.h>
#include <cstdint>

// Problem constants (fixed by the dataset)
#define N_NODES 100000
#define N_EDGES 600000
#define IN_C  128
#define HID_C 128
#define OUT_C 64

#define SCAN_BLK 1024
#define SCAN_NB  ((N_NODES + SCAN_BLK - 1) / SCAN_BLK)

// ===================== scratch (static device globals) ======================
__device__ float g_dinv[N_NODES];
__device__ int   g_cnt [N_NODES];          // in-degree (no self loop)
__device__ int   g_rs  [N_NODES];          // row start (exclusive prefix of cnt)
__device__ int   g_fill[N_NODES];          // fill cursor
__device__ int   g_bsum[SCAN_NB];          // scan block sums
__device__ int   g_boff[SCAN_NB];          // scanned block offsets
__device__ int   g_csr_src[N_EDGES];       // src ids grouped by dst
__device__ float g_h1s [(size_t)N_NODES * HID_C];  // (x@W1) * dinv[row]
__device__ float g_a1  [(size_t)N_NODES * HID_C];  // relu-activated layer-1 out
__device__ float g_h2s [(size_t)N_NODES * OUT_C];  // (a1@W2) * dinv[row]

// Pre-swizzled transposed split weights: row n (output ch), 128 bf16 k's,
// 256 B/row, 16B-block XOR swizzle: blk' = blk ^ (n & 7).
__device__ __align__(128) unsigned char g_B1hi[HID_C * 256];   // 32768 B
__device__ __align__(128) unsigned char g_B1lo[HID_C * 256];
__device__ __align__(128) unsigned char g_B2hi[OUT_C * 256];   // 16384 B
__device__ __align__(128) unsigned char g_B2lo[OUT_C * 256];

__device__ __forceinline__ uint32_t sw_off(int row, int k) {
    return (uint32_t)row * 256u + ((((uint32_t)k >> 3) ^ ((uint32_t)row & 7u)) << 4)
         + ((uint32_t)k & 7u) * 2u;
}

__device__ __forceinline__ uint32_t smem_u32(const void* p) {
    uint32_t a;
    asm("{ .reg .u64 t; cvta.to.shared.u64 t, %1; cvt.u32.u64 %0, t; }" : "=r"(a) : "l"(p));
    return a;
}

__device__ __forceinline__ void ldsm_x4(uint32_t& r0, uint32_t& r1,
                                        uint32_t& r2, uint32_t& r3, uint32_t addr) {
    asm volatile("ldmatrix.sync.aligned.m8n8.x4.shared.b16 {%0,%1,%2,%3}, [%4];"
                 : "=r"(r0), "=r"(r1), "=r"(r2), "=r"(r3) : "r"(addr));
}

__device__ __forceinline__ void mma_bf16(float& c0, float& c1, float& c2, float& c3,
                                         uint32_t a0, uint32_t a1, uint32_t a2, uint32_t a3,
                                         uint32_t b0, uint32_t b1) {
    asm volatile("mma.sync.aligned.m16n8k16.row.col.f32.bf16.bf16.f32 "
                 "{%0,%1,%2,%3}, {%4,%5,%6,%7}, {%8,%9}, {%0,%1,%2,%3};"
                 : "+f"(c0), "+f"(c1), "+f"(c2), "+f"(c3)
                 : "r"(a0), "r"(a1), "r"(a2), "r"(a3), "r"(b0), "r"(b1));
}

__device__ __forceinline__ void split2(float a, float b, uint32_t& hi, uint32_t& lo) {
    __nv_bfloat16 ha = __float2bfloat16(a);
    __nv_bfloat16 hb = __float2bfloat16(b);
    __nv_bfloat162 h = __halves2bfloat162(ha, hb);
    __nv_bfloat162 l = __halves2bfloat162(__float2bfloat16(a - __bfloat162float(ha)),
                                          __float2bfloat16(b - __bfloat162float(hb)));
    hi = *(uint32_t*)&h;
    lo = *(uint32_t*)&l;
}

// ===================== weight prep: transpose + bf16 split + swizzle ========
__global__ void prep_kernel(const float* __restrict__ W1,
                            const float* __restrict__ W2) {
    const int i = blockIdx.x * blockDim.x + threadIdx.x;
    if (i < IN_C * HID_C) {
        const int k = i >> 7;        // input channel
        const int n = i & 127;       // output channel
        const float v = W1[k * HID_C + n];
        const __nv_bfloat16 h = __float2bfloat16(v);
        const __nv_bfloat16 l = __float2bfloat16(v - __bfloat162float(h));
        const uint32_t off = sw_off(n, k);
        *(__nv_bfloat16*)(g_B1hi + off) = h;
        *(__nv_bfloat16*)(g_B1lo + off) = l;
    } else if (i < IN_C * HID_C + HID_C * OUT_C) {
        const int j = i - IN_C * HID_C;
        const int k = j >> 6;
        const int n = j & 63;
        const float v = W2[k * OUT_C + n];
        const __nv_bfloat16 h = __float2bfloat16(v);
        const __nv_bfloat16 l = __float2bfloat16(v - __bfloat162float(h));
        const uint32_t off = sw_off(n, k);
        *(__nv_bfloat16*)(g_B2hi + off) = h;
        *(__nv_bfloat16*)(g_B2lo + off) = l;
    }
}

// ===================== CSR build ============================================
__global__ void zero_kernel(int n) {
    int i = blockIdx.x * blockDim.x + threadIdx.x;
    if (i < n) { g_cnt[i] = 0; g_fill[i] = 0; }
}

__global__ void count_kernel(const int* __restrict__ dst, int E) {
    int e = blockIdx.x * blockDim.x + threadIdx.x;
    if (e < E) atomicAdd(&g_cnt[dst[e]], 1);
}

__global__ void dinv_kernel(int n) {
    int i = blockIdx.x * blockDim.x + threadIdx.x;
    if (i < n) g_dinv[i] = rsqrtf((float)(g_cnt[i] + 1));  // +1 self loop
}

// per-block exclusive scan of g_cnt -> g_rs (partial), block sums -> g_bsum
__global__ void scan1_kernel(int n) {
    __shared__ int sh[SCAN_BLK];
    const int i = blockIdx.x * SCAN_BLK + threadIdx.x;
    const int v = (i < n) ? g_cnt[i] : 0;
    sh[threadIdx.x] = v;
    __syncthreads();
    for (int off = 1; off < SCAN_BLK; off <<= 1) {
        int t = (threadIdx.x >= off) ? sh[threadIdx.x - off] : 0;
        __syncthreads();
        sh[threadIdx.x] += t;
        __syncthreads();
    }
    if (i < n) g_rs[i] = sh[threadIdx.x] - v;  // exclusive
    if (threadIdx.x == SCAN_BLK - 1) g_bsum[blockIdx.x] = sh[threadIdx.x];
}

__global__ void scan2_kernel() {
    if (threadIdx.x == 0) {
        int acc = 0;
        for (int b = 0; b < SCAN_NB; b++) { g_boff[b] = acc; acc += g_bsum[b]; }
    }
}

__global__ void scan3_kernel(int n) {
    const int i = blockIdx.x * SCAN_BLK + threadIdx.x;
    if (i < n) g_rs[i] += g_boff[blockIdx.x];
}

__global__ void fill_kernel(const int* __restrict__ src,
                            const int* __restrict__ dst, int E) {
    int e = blockIdx.x * blockDim.x + threadIdx.x;
    if (e < E) {
        const int d = dst[e];
        const int pos = g_rs[d] + atomicAdd(&g_fill[d], 1);
        g_csr_src[pos] = src[e];
    }
}

// ===================== GEMM core (warp mma, bf16 split, 3 terms) ============
// 256 threads = 8 warps, warp grid 4(M) x 2(N). M_TILE = 128 rows.
template <int NC, int NT>
__device__ __forceinline__ void gemm_compute_epilogue(
    uint32_t sA_hi, uint32_t sA_lo, uint32_t sB_hi, uint32_t sB_lo,
    int block_row, int n_nodes, float* __restrict__ gh)
{
    const int tid = threadIdx.x;
    const int wid = tid >> 5;
    const int l   = tid & 31;
    const int mw  = wid >> 1;
    const int nw  = wid & 1;
    const int mbase = mw * 32;
    const int nbase = nw * (NT * 8);
    const int tg = l >> 2;
    const int tp = l & 3;

    float acc[2][NT][4];
#pragma unroll
    for (int mt = 0; mt < 2; mt++)
#pragma unroll
        for (int nt = 0; nt < NT; nt++)
#pragma unroll
            for (int c = 0; c < 4; c++) acc[mt][nt][c] = 0.0f;

    const int a_row_in = l & 15;
    const int a_kb_add = l >> 4;
    const int b_nrow   = l & 7;
    const int b_nt_add = l >> 4;
    const int b_kb_add = (l >> 3) & 1;

#pragma unroll
    for (int ks = 0; ks < 8; ks++) {
        const int kb0 = ks * 2;
        uint32_t ah[2][4], al[2][4];
#pragma unroll
        for (int mt = 0; mt < 2; mt++) {
            const int row = mbase + mt * 16 + a_row_in;
            const uint32_t off = (uint32_t)row * 256u
                + ((uint32_t)((kb0 + a_kb_add) ^ (row & 7)) << 4);
            ldsm_x4(ah[mt][0], ah[mt][1], ah[mt][2], ah[mt][3], sA_hi + off);
            ldsm_x4(al[mt][0], al[mt][1], al[mt][2], al[mt][3], sA_lo + off);
        }
        uint32_t bh[NT][2], bl[NT][2];
#pragma unroll
        for (int j = 0; j < NT / 2; j++) {
            const int n = nbase + (2 * j + b_nt_add) * 8 + b_nrow;
            const uint32_t off = (uint32_t)n * 256u
                + ((uint32_t)((kb0 + b_kb_add) ^ (n & 7)) << 4);
            ldsm_x4(bh[2*j][0], bh[2*j][1], bh[2*j+1][0], bh[2*j+1][1], sB_hi + off);
            ldsm_x4(bl[2*j][0], bl[2*j][1], bl[2*j+1][0], bl[2*j+1][1], sB_lo + off);
        }
#pragma unroll
        for (int mt = 0; mt < 2; mt++)
#pragma unroll
            for (int nt = 0; nt < NT; nt++) {
                mma_bf16(acc[mt][nt][0], acc[mt][nt][1], acc[mt][nt][2], acc[mt][nt][3],
                         ah[mt][0], ah[mt][1], ah[mt][2], ah[mt][3], bh[nt][0], bh[nt][1]);
                mma_bf16(acc[mt][nt][0], acc[mt][nt][1], acc[mt][nt][2], acc[mt][nt][3],
                         al[mt][0], al[mt][1], al[mt][2], al[mt][3], bh[nt][0], bh[nt][1]);
                mma_bf16(acc[mt][nt][0], acc[mt][nt][1], acc[mt][nt][2], acc[mt][nt][3],
                         ah[mt][0], ah[mt][1], ah[mt][2], ah[mt][3], bl[nt][0], bl[nt][1]);
            }
    }

    // Epilogue: gh = acc * dinv[row]
#pragma unroll
    for (int mt = 0; mt < 2; mt++) {
        const int r0 = block_row + mbase + mt * 16 + tg;
        const int r1 = r0 + 8;
        const bool v0 = r0 < n_nodes;
        const bool v1 = r1 < n_nodes;
        const float d0 = v0 ? g_dinv[r0] : 0.0f;
        const float d1 = v1 ? g_dinv[r1] : 0.0f;
#pragma unroll
        for (int nt = 0; nt < NT; nt++) {
            const int col = nbase + nt * 8 + tp * 2;
            if (v0) {
                float2 o; o.x = acc[mt][nt][0] * d0; o.y = acc[mt][nt][1] * d0;
                *(float2*)&gh[(size_t)r0 * NC + col] = o;
            }
            if (v1) {
                float2 o; o.x = acc[mt][nt][2] * d1; o.y = acc[mt][nt][3] * d1;
                *(float2*)&gh[(size_t)r1 * NC + col] = o;
            }
        }
    }
}

// ===================== GEMM1: h1s = (x@W1)*dinv ============================
__global__ __launch_bounds__(256) void gemm1_kernel(const float* __restrict__ x,
                                                    int n_nodes) {
    extern __shared__ char smem[];
    const uint32_t sbase = smem_u32(smem);
    const uint32_t sA_hi = sbase;
    const uint32_t sA_lo = sbase + 32768;
    const uint32_t sB_hi = sbase + 65536;
    const uint32_t sB_lo = sbase + 98304;

    const int tid = threadIdx.x;
    const int block_row = blockIdx.x * 128;

    {
        const uint4* sh = (const uint4*)g_B1hi;
        const uint4* sl = (const uint4*)g_B1lo;
        uint4* dh = (uint4*)(smem + 65536);
        uint4* dl = (uint4*)(smem + 98304);
#pragma unroll
        for (int i = tid; i < 2048; i += 256) { dh[i] = sh[i]; dl[i] = sl[i]; }
    }

    {
        const int l = tid & 31;
        const int w = tid >> 5;
        uint2* Ah = (uint2*)smem;
        uint2* Al = (uint2*)(smem + 32768);
#pragma unroll
        for (int p = 0; p < 16; p++) {
            const int r = w + 8 * p;
            const int grow = block_row + r;
            float4 v = make_float4(0.f, 0.f, 0.f, 0.f);
            if (grow < n_nodes) v = *(const float4*)&x[(size_t)grow * IN_C + 4 * l];
            uint2 h, lo;
            split2(v.x, v.y, h.x, lo.x);
            split2(v.z, v.w, h.y, lo.y);
            const uint32_t off = ((uint32_t)r * 256u
                + ((uint32_t)((l >> 1) ^ (r & 7)) << 4) + (uint32_t)(l & 1) * 8u) >> 3;
            Ah[off] = h;
            Al[off] = lo;
        }
    }
    __syncthreads();

    gemm_compute_epilogue<HID_C, 8>(sA_hi, sA_lo, sB_hi, sB_lo,
                                    block_row, n_nodes, g_h1s);
}

// ===================== AGG1: a1 = relu(dinv*(h1s[d] + sum_in h1s[s]) + b1) ==
__global__ __launch_bounds__(256) void agg1_kernel(const float* __restrict__ b1,
                                                   int n_nodes) {
    const int gid  = blockIdx.x * blockDim.x + threadIdx.x;
    const int node = gid >> 5;
    if (node >= n_nodes) return;
    const int lane = gid & 31;

    const int beg = g_rs[node];
    const int end = beg + g_cnt[node];

    float4 acc = *(const float4*)&g_h1s[(size_t)node * HID_C + lane * 4];  // self
    float4 acc2 = make_float4(0.f, 0.f, 0.f, 0.f);

    int e = beg;
    for (; e + 1 < end; e += 2) {
        const int s0 = __ldg(&g_csr_src[e]);
        const int s1 = __ldg(&g_csr_src[e + 1]);
        const float4 v0 = *(const float4*)&g_h1s[(size_t)s0 * HID_C + lane * 4];
        const float4 v1 = *(const float4*)&g_h1s[(size_t)s1 * HID_C + lane * 4];
        acc.x += v0.x; acc.y += v0.y; acc.z += v0.z; acc.w += v0.w;
        acc2.x += v1.x; acc2.y += v1.y; acc2.z += v1.z; acc2.w += v1.w;
    }
    if (e < end) {
        const int s0 = __ldg(&g_csr_src[e]);
        const float4 v0 = *(const float4*)&g_h1s[(size_t)s0 * HID_C + lane * 4];
        acc.x += v0.x; acc.y += v0.y; acc.z += v0.z; acc.w += v0.w;
    }
    acc.x += acc2.x; acc.y += acc2.y; acc.z += acc2.z; acc.w += acc2.w;

    const float di = g_dinv[node];
    const float4 b = *(const float4*)&b1[lane * 4];
    float4 o;
    o.x = fmaxf(di * acc.x + b.x, 0.0f);
    o.y = fmaxf(di * acc.y + b.y, 0.0f);
    o.z = fmaxf(di * acc.z + b.z, 0.0f);
    o.w = fmaxf(di * acc.w + b.w, 0.0f);
    *(float4*)&g_a1[(size_t)node * HID_C + lane * 4] = o;
}

// ===================== GEMM2: h2s = (a1@W2)*dinv ============================
__global__ __launch_bounds__(256) void gemm2_kernel(int n_nodes) {
    extern __shared__ char smem[];
    const uint32_t sbase = smem_u32(smem);
    const uint32_t sA_hi = sbase;
    const uint32_t sA_lo = sbase + 32768;
    const uint32_t sB_hi = sbase + 65536;
    const uint32_t sB_lo = sbase + 81920;

    const int tid = threadIdx.x;
    const int block_row = blockIdx.x * 128;

    {
        const uint4* sh = (const uint4*)g_B2hi;
        const uint4* sl = (const uint4*)g_B2lo;
        uint4* dh = (uint4*)(smem + 65536);
        uint4* dl = (uint4*)(smem + 81920);
#pragma unroll
        for (int i = tid; i < 1024; i += 256) { dh[i] = sh[i]; dl[i] = sl[i]; }
    }

    {
        const int l = tid & 31;
        const int w = tid >> 5;
        uint2* Ah = (uint2*)smem;
        uint2* Al = (uint2*)(smem + 32768);
#pragma unroll
        for (int p = 0; p < 16; p++) {
            const int r = w + 8 * p;
            const int grow = block_row + r;
            float4 a = make_float4(0.f, 0.f, 0.f, 0.f);
            if (grow < n_nodes)
                a = *(const float4*)&g_a1[(size_t)grow * HID_C + 4 * l];
            uint2 h2, lo;
            split2(a.x, a.y, h2.x, lo.x);
            split2(a.z, a.w, h2.y, lo.y);
            const uint32_t off = ((uint32_t)r * 256u
                + ((uint32_t)((l >> 1) ^ (r & 7)) << 4) + (uint32_t)(l & 1) * 8u) >> 3;
            Ah[off] = h2;
            Al[off] = lo;
        }
    }
    __syncthreads();

    gemm_compute_epilogue<OUT_C, 4>(sA_hi, sA_lo, sB_hi, sB_lo,
                                    block_row, n_nodes, g_h2s);
}

// ===================== AGG2: out = dinv*(h2s[d] + sum_in h2s[s]) + b2 =======
__global__ __launch_bounds__(256) void agg2_kernel(const float* __restrict__ b2,
                                                   float* __restrict__ out,
                                                   int n_nodes) {
    const int gid  = blockIdx.x * blockDim.x + threadIdx.x;
    const int node = gid >> 4;
    if (node >= n_nodes) return;
    const int lane = gid & 15;

    const int beg = g_rs[node];
    const int end = beg + g_cnt[node];

    float4 acc = *(const float4*)&g_h2s[(size_t)node * OUT_C + lane * 4];  // self
    float4 acc2 = make_float4(0.f, 0.f, 0.f, 0.f);

    int e = beg;
    for (; e + 1 < end; e += 2) {
        const int s0 = __ldg(&g_csr_src[e]);
        const int s1 = __ldg(&g_csr_src[e + 1]);
        const float4 v0 = *(const float4*)&g_h2s[(size_t)s0 * OUT_C + lane * 4];
        const float4 v1 = *(const float4*)&g_h2s[(size_t)s1 * OUT_C + lane * 4];
        acc.x += v0.x; acc.y += v0.y; acc.z += v0.z; acc.w += v0.w;
        acc2.x += v1.x; acc2.y += v1.y; acc2.z += v1.z; acc2.w += v1.w;
    }
    if (e < end) {
        const int s0 = __ldg(&g_csr_src[e]);
        const float4 v0 = *(const float4*)&g_h2s[(size_t)s0 * OUT_C + lane * 4];
        acc.x += v0.x; acc.y += v0.y; acc.z += v0.z; acc.w += v0.w;
    }
    acc.x += acc2.x; acc.y += acc2.y; acc.z += acc2.z; acc.w += acc2.w;

    const float di = g_dinv[node];
    const float4 b = *(const float4*)&b2[lane * 4];
    float4 o;
    o.x = di * acc.x + b.x;
    o.y = di * acc.y + b.y;
    o.z = di * acc.z + b.z;
    o.w = di * acc.w + b.w;
    *(float4*)&out[(size_t)node * OUT_C + lane * 4] = o;
}

// ===================== launch ===============================================
extern "C" void kernel_launch(void* const* d_in, const int* in_sizes, int n_in,
                              void* d_out, int out_size) {
    const float* x   = (const float*)d_in[0];
    const float* W1  = (const float*)d_in[1];
    const float* b1  = (const float*)d_in[2];
    const float* W2  = (const float*)d_in[3];
    const float* b2  = (const float*)d_in[4];
    const int*   src = (const int*)  d_in[5];
    const int*   dst = (const int*)  d_in[6];
    float*       out = (float*)d_out;

    const int n = in_sizes[0] / IN_C;   // 100000
    const int E = in_sizes[5];          // 600000

    static bool attr_done = false;
    if (!attr_done) {
        cudaFuncSetAttribute(gemm1_kernel,
                             cudaFuncAttributeMaxDynamicSharedMemorySize, 131072);
        cudaFuncSetAttribute(gemm2_kernel,
                             cudaFuncAttributeMaxDynamicSharedMemorySize, 98304);
        attr_done = true;
    }

    // weight prep + CSR build + dinv
    prep_kernel<<<(IN_C * HID_C + HID_C * OUT_C + 255) / 256, 256>>>(W1, W2);
    zero_kernel<<<(n + 255) / 256, 256>>>(n);
    count_kernel<<<(E + 255) / 256, 256>>>(dst, E);
    dinv_kernel<<<(n + 255) / 256, 256>>>(n);
    scan1_kernel<<<SCAN_NB, SCAN_BLK>>>(n);
    scan2_kernel<<<1, 32>>>();
    scan3_kernel<<<SCAN_NB, SCAN_BLK>>>(n);
    fill_kernel<<<(E + 255) / 256, 256>>>(src, dst, E);

    const int tiles = (n + 127) / 128;

    // layer 1
    gemm1_kernel<<<tiles, 256, 131072>>>(x, n);
    {
        long long threads = (long long)n * 32;
        agg1_kernel<<<(int)((threads + 255) / 256), 256>>>(b1, n);
    }

    // layer 2
    gemm2_kernel<<<tiles, 256, 98304>>>(n);
    {
        long long threads = (long long)n * 16;
        agg2_kernel<<<(int)((threads + 255) / 256), 256>>>(b2, out, n);
    }
}